// round 9
// baseline (speedup 1.0000x reference)
#include <cuda_runtime.h>
#include <cuda_bf16.h>
#include <cstdint>

// Problem constants (shapes are fixed by the reference)
#define NN      10000
#define EE      640000
#define TOT_E   (EE + NN)      // edges + self loops
#define IN_FT   512
#define OUT_FT  128

#define BM 32
#define BK 32
#define NKT (IN_FT / BK)       // 16 k-tiles
#define MAXD 512
#define SCAN_TOT 10240         // padded count array (40 * 256 >= NN)
#define NBLK 40                // scan blocks

// ---------------- device scratch (no allocation allowed) ----------------
__device__ float g_h[NN * OUT_FT];         // h = seq @ W_comb^T
__device__ float g_wcT[IN_FT * OUT_FT];    // W_comb transposed: [k][o]
__device__ float g_as[NN];                 // h @ att_src
__device__ float g_ad[NN];                 // h @ att_dst
__device__ int   g_cnt[SCAN_TOT];          // per-dst counts; ZERO at call entry
                                           // (module init / re-zeroed by scan)
__device__ int   g_rowptr[NN + 1];         // block-LOCAL exclusive prefixes
__device__ int   g_fill[NN];               // scatter cursors (block-local)
__device__ int   g_blktot[NBLK];           // per-scan-block totals
__device__ int   g_blkoff[NBLK];           // exclusive scan of block totals
__device__ unsigned g_ticket;              // last-block ticket (reset by scan)
__device__ int   g_csr[TOT_E];             // src node id per CSR slot
__device__ int2  g_sd[TOT_E];              // decoded (src, dst)
__device__ int   g_flag = 0;               // 1 = edge_index is int32 (OR-only)

// ---------------- helpers ----------------
__device__ __forceinline__ void cp16(void* dst, const void* src) {
    uint32_t d = (uint32_t)__cvta_generic_to_shared(dst);
    asm volatile("cp.async.cg.shared.global [%0], [%1], 16;\n" :: "r"(d), "l"(src));
}
__device__ __forceinline__ void cp_commit() {
    asm volatile("cp.async.commit_group;\n");
}
template<int N> __device__ __forceinline__ void cp_wait() {
    asm volatile("cp.async.wait_group %0;\n" :: "n"(N));
}

// ---------------- setup: tiled wcomb + dtype detect ----------------
// Blocks 0..31: (8 o-tiles x 4 k-tiles). Each block streams its 64KB W_fc
// k-slice ONCE (vs. old version: every block read all 1MB -> 128MB L2 traffic).
// Block 32: int32-vs-int64 detection.
__global__ __launch_bounds__(128) void setup_kernel(
        const float* __restrict__ Wgat,
        const float* __restrict__ Wfc,
        const int* __restrict__ ep, int E) {
    int b = blockIdx.x;
    if (b < 32) {
        int ot = b >> 2;               // o-tile: 16 outputs
        int kt = b & 3;                // k-tile: 128 k's
        int k  = kt * 128 + threadIdx.x;
        __shared__ float ws[16][128];  // Wgat rows for this o-tile
        for (int i = threadIdx.x; i < 16 * 128; i += 128)
            ws[i >> 7][i & 127] = Wgat[(ot * 16 + (i >> 7)) * OUT_FT + (i & 127)];
        __syncthreads();
        float acc[16];
#pragma unroll
        for (int o = 0; o < 16; o++) acc[o] = 0.f;
#pragma unroll 4
        for (int m = 0; m < OUT_FT; m++) {
            float wf = Wfc[m * IN_FT + k];
#pragma unroll
            for (int o = 0; o < 16; o++) acc[o] += ws[o][m] * wf;
        }
        float* dst = &g_wcT[k * OUT_FT + ot * 16];
#pragma unroll
        for (int q = 0; q < 4; q++)
            *(float4*)(dst + q * 4) =
                make_float4(acc[q*4], acc[q*4+1], acc[q*4+2], acc[q*4+3]);
    } else {
        // detect: int64 node ids < 2^31 have zero high words; int32 data
        // has random node ids there.
#pragma unroll
        for (int i = 0; i < 8; i++) {
            int j = threadIdx.x * 8 + i;
            if (j < 1024 && j < E && ep[2 * j + 1] != 0) {
                atomicOr(&g_flag, 1);
                break;
            }
        }
    }
}

// decode edges (4 per thread, vectorized), count degrees, stage (src,dst)
__global__ void count_kernel(const void* eidx, int E, int n) {
    int t = blockIdx.x * blockDim.x + threadIdx.x;
    int quarter = E >> 2;
    int rem = E & 3;
    if (t < quarter) {
        int s[4], d[4];
        if (g_flag) {
            int4 ss = ((const int4*)eidx)[t];
            int4 dd = ((const int4*)((const int*)eidx + E))[t];
            s[0] = ss.x; s[1] = ss.y; s[2] = ss.z; s[3] = ss.w;
            d[0] = dd.x; d[1] = dd.y; d[2] = dd.z; d[3] = dd.w;
        } else {
            const longlong2* sp = (const longlong2*)eidx;
            const longlong2* dp = (const longlong2*)((const long long*)eidx + E);
            longlong2 s01 = sp[2 * t], s23 = sp[2 * t + 1];
            longlong2 d01 = dp[2 * t], d23 = dp[2 * t + 1];
            s[0] = (int)s01.x; s[1] = (int)s01.y; s[2] = (int)s23.x; s[3] = (int)s23.y;
            d[0] = (int)d01.x; d[1] = (int)d01.y; d[2] = (int)d23.x; d[3] = (int)d23.y;
        }
        *(int4*)&g_sd[4 * t]     = make_int4(s[0], d[0], s[1], d[1]);
        *(int4*)&g_sd[4 * t + 2] = make_int4(s[2], d[2], s[3], d[3]);
        atomicAdd(&g_cnt[d[0]], 1);
        atomicAdd(&g_cnt[d[1]], 1);
        atomicAdd(&g_cnt[d[2]], 1);
        atomicAdd(&g_cnt[d[3]], 1);
    } else if (t < quarter + rem) {
        int e = E - rem + (t - quarter);
        int s, d;
        if (g_flag) {
            const int* q = (const int*)eidx;
            s = q[e]; d = q[E + e];
        } else {
            const long long* q = (const long long*)eidx;
            s = (int)q[e]; d = (int)q[E + e];
        }
        g_sd[e] = make_int2(s, d);
        atomicAdd(&g_cnt[d], 1);
    } else {
        int node = t - quarter - rem;
        if (node < n) {                // self loops
            g_sd[E + node] = make_int2(node, node);
            atomicAdd(&g_cnt[node], 1);
        }
    }
}

// 40-block scan: each block scans its 256 counts (block-local exclusive
// prefixes into g_rowptr/g_fill), last block (ticket) scans the 40 totals.
// Also RE-ZEROES g_cnt and g_ticket for the next call (invariant restore).
__global__ __launch_bounds__(256) void scan_kernel(int n) {
    __shared__ int wsum[8];
    __shared__ int lastflag;
    int b = blockIdx.x, t = threadIdx.x;
    int lane = t & 31, w = t >> 5;
    int idx = b * 256 + t;

    int v = g_cnt[idx];
    g_cnt[idx] = 0;                    // restore zero-invariant for next call
    // inclusive warp scan
    int incl = v;
#pragma unroll
    for (int o = 1; o < 32; o <<= 1) {
        int x = __shfl_up_sync(0xffffffffu, incl, o);
        if (lane >= o) incl += x;
    }
    if (lane == 31) wsum[w] = incl;
    __syncthreads();
    int woff = 0;
#pragma unroll
    for (int j = 0; j < 8; j++) woff += (j < w) ? wsum[j] : 0;
    int excl = woff + incl - v;        // block-local exclusive prefix

    if (idx <= n) g_rowptr[idx] = excl;
    if (idx < n)  g_fill[idx]   = excl;

    // block total -> last block computes block offsets
    if (t == 0) {
        int tot = 0;
#pragma unroll
        for (int j = 0; j < 8; j++) tot += wsum[j];
        g_blktot[b] = tot;
        __threadfence();
        unsigned tk = atomicAdd(&g_ticket, 1u);
        lastflag = (tk == NBLK - 1);
    }
    __syncthreads();
    if (lastflag && t == 0) {
        int run = 0;
#pragma unroll
        for (int j = 0; j < NBLK; j++) {
            g_blkoff[j] = run;
            run += g_blktot[j];
        }
        g_ticket = 0;                  // reset for next call
    }
}

// scatter srcs into CSR slots (2 edges per thread); global pos = local + blkoff
__global__ void scatter_kernel(int tot) {
    int t = blockIdx.x * blockDim.x + threadIdx.x;
    int half = tot >> 1;
    if (t < half) {
        int4 p = *(const int4*)&g_sd[2 * t];   // (s0,d0,s1,d1)
        int pos0 = atomicAdd(&g_fill[p.y], 1) + g_blkoff[p.y >> 8];
        g_csr[pos0] = p.x;
        int pos1 = atomicAdd(&g_fill[p.w], 1) + g_blkoff[p.w >> 8];
        g_csr[pos1] = p.z;
    } else if (2 * half + (t - half) < tot) {  // odd tail
        int2 p = g_sd[2 * half + (t - half)];
        int pos = atomicAdd(&g_fill[p.y], 1) + g_blkoff[p.y >> 8];
        g_csr[pos] = p.x;
    }
}

// h = seq @ W_comb^T.  BM=32 x 128 x BK=32, 128 threads, 4x8 microtile,
// cp.async double-buffered smem.  Fused epilogue computes a_s/a_d.
__global__ __launch_bounds__(128, 4) void gemm_h_kernel(
        const float* __restrict__ seq,
        const float* __restrict__ att_s,
        const float* __restrict__ att_d, int n) {
    __shared__ float As[2][BM][36];      // pitch 36 floats (16B-aligned rows)
    __shared__ float Bs[2][BK][OUT_FT];

    int bm  = blockIdx.x * BM;
    int tid = threadIdx.x;
    int tx  = tid & 15;          // col group
    int ty  = tid >> 4;          // 0..7 -> 4 rows each
    int r0  = ty * 4;

    auto issue = [&](int kt, int buf) {
        int k0 = kt * BK;
#pragma unroll
        for (int i = 0; i < 2; i++) {                 // A: 32x32 = 256 x 16B
            int idx = tid + i * 128;
            int r = idx >> 3, c4 = (idx & 7) << 2;
            int row = bm + r; if (row >= n) row = n - 1;
            cp16(&As[buf][r][c4], &seq[row * IN_FT + k0 + c4]);
        }
#pragma unroll
        for (int i = 0; i < 8; i++) {                 // B: 32x128 = 1024 x 16B
            int idx = tid + i * 128;
            int kk = idx >> 5, o4 = (idx & 31) << 2;
            cp16(&Bs[buf][kk][o4], &g_wcT[(k0 + kk) * OUT_FT + o4]);
        }
        cp_commit();
    };

    float acc[4][8];
#pragma unroll
    for (int i = 0; i < 4; i++)
#pragma unroll
        for (int j = 0; j < 8; j++) acc[i][j] = 0.f;

    issue(0, 0);
    issue(1, 1);

    for (int kt = 0; kt < NKT; kt++) {
        if (kt < NKT - 1) cp_wait<1>(); else cp_wait<0>();
        __syncthreads();
        int buf = kt & 1;
#pragma unroll
        for (int kk = 0; kk < BK; kk++) {
            float a[4];
#pragma unroll
            for (int i = 0; i < 4; i++) a[i] = As[buf][r0 + i][kk];
            // thread's 8 cols: {tx*4..+3} and {64+tx*4..+3} (conflict-free LDS.128)
            float4 b0 = *(const float4*)&Bs[buf][kk][tx * 4];
            float4 b1 = *(const float4*)&Bs[buf][kk][64 + tx * 4];
            float b[8] = {b0.x, b0.y, b0.z, b0.w, b1.x, b1.y, b1.z, b1.w};
#pragma unroll
            for (int i = 0; i < 4; i++)
#pragma unroll
                for (int j = 0; j < 8; j++)
                    acc[i][j] += a[i] * b[j];
        }
        __syncthreads();
        if (kt + 2 < NKT) issue(kt + 2, buf);
    }

    // epilogue: store h + fused attention logits
    float as8[8], ad8[8];
#pragma unroll
    for (int j = 0; j < 4; j++) {
        as8[j]     = att_s[tx * 4 + j];
        as8[4 + j] = att_s[64 + tx * 4 + j];
        ad8[j]     = att_d[tx * 4 + j];
        ad8[4 + j] = att_d[64 + tx * 4 + j];
    }
#pragma unroll
    for (int i = 0; i < 4; i++) {
        int row = bm + r0 + i;
        bool valid = (row < n);
        float vs = 0.f, vd = 0.f;
#pragma unroll
        for (int j = 0; j < 8; j++) { vs += acc[i][j] * as8[j]; vd += acc[i][j] * ad8[j]; }
        if (valid) {
            *(float4*)&g_h[row * OUT_FT + tx * 4]      =
                make_float4(acc[i][0], acc[i][1], acc[i][2], acc[i][3]);
            *(float4*)&g_h[row * OUT_FT + 64 + tx * 4] =
                make_float4(acc[i][4], acc[i][5], acc[i][6], acc[i][7]);
        }
#pragma unroll
        for (int o = 1; o < 16; o <<= 1) {
            vs += __shfl_xor_sync(0xffffffffu, vs, o);
            vd += __shfl_xor_sync(0xffffffffu, vd, o);
        }
        if (valid && tx == 0) { g_as[row] = vs; g_ad[row] = vd; }
    }
}

// One block (128 threads) per destination node: segment softmax + weighted sum.
__global__ __launch_bounds__(128) void aggregate_kernel(
        const float* __restrict__ gat_bias,
        const float* __restrict__ bias,
        const float* __restrict__ prelu_a,
        float* __restrict__ out, int n) {
    int d = blockIdx.x;
    if (d >= n) return;
    int tid   = threadIdx.x;
    int w     = tid >> 5, lane = tid & 31;
    int start = g_rowptr[d]     + g_blkoff[d >> 8];
    int end   = g_rowptr[d + 1] + g_blkoff[(d + 1) >> 8];
    int deg   = end - start;
    float ad  = g_ad[d];

    __shared__ float e_sh[MAXD];
    __shared__ int   s_sh[MAXD];
    __shared__ float red[4];
    __shared__ float accsh[4][OUT_FT];

    if (deg <= MAXD) {
        // load + leaky-relu + max
        float lm = -1e30f;
        for (int i = tid; i < deg; i += 128) {
            int s = g_csr[start + i];
            float e = g_as[s] + ad;
            e = (e >= 0.f) ? e : 0.2f * e;
            s_sh[i] = s; e_sh[i] = e;
            lm = fmaxf(lm, e);
        }
#pragma unroll
        for (int o = 16; o > 0; o >>= 1)
            lm = fmaxf(lm, __shfl_xor_sync(0xffffffffu, lm, o));
        if (lane == 0) red[w] = lm;
        __syncthreads();
        float m = fmaxf(fmaxf(red[0], red[1]), fmaxf(red[2], red[3]));
        __syncthreads();

        // exp + denom
        float ls = 0.f;
        for (int i = tid; i < deg; i += 128) {
            float p = __expf(e_sh[i] - m);
            e_sh[i] = p;
            ls += p;
        }
#pragma unroll
        for (int o = 16; o > 0; o >>= 1)
            ls += __shfl_xor_sync(0xffffffffu, ls, o);
        if (lane == 0) red[w] = ls;
        __syncthreads();
        float denom = red[0] + red[1] + red[2] + red[3];

        // warp-parallel accumulation: warp w takes edges w, w+4, ...; lane = 4 features
        float4 a4 = make_float4(0.f, 0.f, 0.f, 0.f);
        for (int j = w; j < deg; j += 4) {
            float p = e_sh[j];
            const float4 hv = *(const float4*)&g_h[s_sh[j] * OUT_FT + lane * 4];
            a4.x += p * hv.x; a4.y += p * hv.y; a4.z += p * hv.z; a4.w += p * hv.w;
        }
        *(float4*)&accsh[w][lane * 4] = a4;
        __syncthreads();
        float sum = accsh[0][tid] + accsh[1][tid] + accsh[2][tid] + accsh[3][tid];

        float o_ = sum / (denom + 1e-16f) + gat_bias[tid] + bias[tid];
        float a  = prelu_a[0];
        out[d * OUT_FT + tid] = (o_ >= 0.f) ? o_ : a * o_;
    } else {
        // generic fallback: feature-per-thread, chunked path
        float lm = -1e30f;
        for (int i = start + tid; i < end; i += 128) {
            float e = g_as[g_csr[i]] + ad;
            e = (e >= 0.f) ? e : 0.2f * e;
            lm = fmaxf(lm, e);
        }
#pragma unroll
        for (int o = 16; o > 0; o >>= 1)
            lm = fmaxf(lm, __shfl_xor_sync(0xffffffffu, lm, o));
        if (lane == 0) red[w] = lm;
        __syncthreads();
        float m = fmaxf(fmaxf(red[0], red[1]), fmaxf(red[2], red[3]));
        __syncthreads();

        float ls = 0.f;
        for (int i = start + tid; i < end; i += 128) {
            float e = g_as[g_csr[i]] + ad;
            e = (e >= 0.f) ? e : 0.2f * e;
            ls += __expf(e - m);
        }
#pragma unroll
        for (int o = 16; o > 0; o >>= 1)
            ls += __shfl_xor_sync(0xffffffffu, ls, o);
        if (lane == 0) red[w] = ls;
        __syncthreads();
        float denom = red[0] + red[1] + red[2] + red[3];
        __syncthreads();

        float acc = 0.f;
        for (int c = start; c < end; c += 128) {
            int i = c + tid;
            if (i < end) {
                int s = g_csr[i];
                float e = g_as[s] + ad;
                e = (e >= 0.f) ? e : 0.2f * e;
                e_sh[tid] = __expf(e - m);
                s_sh[tid] = s;
            }
            __syncthreads();
            int len = min(128, end - c);
            for (int j = 0; j < len; j++)
                acc += e_sh[j] * g_h[s_sh[j] * OUT_FT + tid];
            __syncthreads();
        }
        float o_ = acc / (denom + 1e-16f) + gat_bias[tid] + bias[tid];
        float a  = prelu_a[0];
        out[d * OUT_FT + tid] = (o_ >= 0.f) ? o_ : a * o_;
    }
}

// ---------------- launch ----------------
extern "C" void kernel_launch(void* const* d_in, const int* in_sizes, int n_in,
                              void* d_out, int out_size) {
    const float* seq      = (const float*)d_in[0];
    const void*  eidx     = d_in[1];
    const float* Wfc      = (const float*)d_in[2];
    const float* Wgat     = (const float*)d_in[3];
    const float* att_src  = (const float*)d_in[4];
    const float* att_dst  = (const float*)d_in[5];
    const float* gat_bias = (const float*)d_in[6];
    const float* bias     = (const float*)d_in[7];
    const float* prelu_a  = (const float*)d_in[8];
    float* out = (float*)d_out;

    int n = in_sizes[0] / IN_FT;     // 10000
    int E = in_sizes[1] / 2;         // 640000
    int tot = E + n;

    setup_kernel<<<33, 128>>>(Wgat, Wfc, (const int*)eidx, E);
    int cnt_threads = E / 4 + (E & 3) + n;
    count_kernel<<<(cnt_threads + 255) / 256, 256>>>(eidx, E, n);
    gemm_h_kernel<<<(n + BM - 1) / BM, 128>>>(seq, att_src, att_dst, n);
    scan_kernel<<<NBLK, 256>>>(n);
    int sc_threads = tot / 2 + 1;
    scatter_kernel<<<(sc_threads + 255) / 256, 256>>>(tot);
    aggregate_kernel<<<n, 128>>>(gat_bias, bias, prelu_a, out, n);
}

// round 11
// speedup vs baseline: 1.1072x; 1.1072x over previous
#include <cuda_runtime.h>
#include <cuda_bf16.h>
#include <cuda_fp16.h>
#include <cstdint>

// Problem constants (shapes are fixed by the reference)
#define NN      10000
#define EE      640000
#define TOT_E   (EE + NN)      // edges + self loops
#define IN_FT   512
#define OUT_FT  128

#define BM 32
#define BK 32
#define NKT (IN_FT / BK)       // 16 k-tiles
#define MAXD 512
#define SCAN_TOT 10240         // padded count array (40 * 256 >= NN)
#define NBLK 40                // scan blocks

// ---------------- device scratch (no allocation allowed) ----------------
__device__ __half g_hh[NN * OUT_FT];       // h in fp16 (aggregate gathers)
__device__ float g_wcT[IN_FT * OUT_FT];    // W_comb transposed: [k][o]
__device__ float g_as[NN];                 // h @ att_src (fp32)
__device__ float g_ad[NN];                 // h @ att_dst (fp32)
__device__ int   g_cnt[SCAN_TOT];          // per-dst counts; ZERO at call entry
                                           // (module init / re-zeroed by scan)
__device__ int   g_rowptr[NN + 1];         // block-LOCAL exclusive prefixes
__device__ int   g_fill[NN];               // scatter cursors (block-local)
__device__ int   g_blktot[NBLK];           // per-scan-block totals
__device__ int   g_blkoff[NBLK];           // exclusive scan of block totals
__device__ unsigned g_ticket;              // last-block ticket (reset by scan)
__device__ int   g_csr[TOT_E];             // src node id per CSR slot
__device__ int2  g_sd[TOT_E];              // decoded (src, dst)
__device__ int   g_flag = 0;               // 1 = edge_index is int32 (OR-only)

// ---------------- helpers ----------------
__device__ __forceinline__ void cp16(void* dst, const void* src) {
    uint32_t d = (uint32_t)__cvta_generic_to_shared(dst);
    asm volatile("cp.async.cg.shared.global [%0], [%1], 16;\n" :: "r"(d), "l"(src));
}
__device__ __forceinline__ void cp_commit() {
    asm volatile("cp.async.commit_group;\n");
}
template<int N> __device__ __forceinline__ void cp_wait() {
    asm volatile("cp.async.wait_group %0;\n" :: "n"(N));
}
__device__ __forceinline__ uint32_t h2_bits(__half2 h) {
    return *reinterpret_cast<uint32_t*>(&h);
}

// ---------------- setup: tiled wcomb (128 blocks) + dtype detect ----------------
// Blocks 0..127: 32 o-tiles (4 outputs) x 4 k-tiles (128 k's). unroll-8 m-loop
// gives MLP=8; ~1 block/SM. Traffic ~8MB, latency-hidden.
// Block 128: int32-vs-int64 detection.
__global__ __launch_bounds__(128) void setup_kernel(
        const float* __restrict__ Wgat,
        const float* __restrict__ Wfc,
        const int* __restrict__ ep, int E) {
    int b = blockIdx.x;
    if (b < 128) {
        int ot = b >> 2;               // o-tile: 4 outputs
        int kt = b & 3;                // k-tile: 128 k's
        int k  = kt * 128 + threadIdx.x;
        __shared__ float ws[4][128];   // Wgat rows for this o-tile
        for (int i = threadIdx.x; i < 4 * 128; i += 128)
            ws[i >> 7][i & 127] = Wgat[(ot * 4 + (i >> 7)) * OUT_FT + (i & 127)];
        __syncthreads();
        float acc[4] = {0.f, 0.f, 0.f, 0.f};
#pragma unroll 8
        for (int m = 0; m < OUT_FT; m++) {
            float wf = Wfc[m * IN_FT + k];
#pragma unroll
            for (int o = 0; o < 4; o++) acc[o] += ws[o][m] * wf;
        }
        *(float4*)&g_wcT[k * OUT_FT + ot * 4] =
            make_float4(acc[0], acc[1], acc[2], acc[3]);
    } else {
        // detect: int64 node ids < 2^31 have zero high words; int32 data
        // has random node ids there.
#pragma unroll
        for (int i = 0; i < 8; i++) {
            int j = threadIdx.x * 8 + i;
            if (j < 1024 && j < E && ep[2 * j + 1] != 0) {
                atomicOr(&g_flag, 1);
                break;
            }
        }
    }
}

// decode edges (4 per thread, vectorized), count degrees, stage (src,dst)
__global__ void count_kernel(const void* eidx, int E, int n) {
    int t = blockIdx.x * blockDim.x + threadIdx.x;
    int quarter = E >> 2;
    int rem = E & 3;
    if (t < quarter) {
        int s[4], d[4];
        if (g_flag) {
            int4 ss = ((const int4*)eidx)[t];
            int4 dd = ((const int4*)((const int*)eidx + E))[t];
            s[0] = ss.x; s[1] = ss.y; s[2] = ss.z; s[3] = ss.w;
            d[0] = dd.x; d[1] = dd.y; d[2] = dd.z; d[3] = dd.w;
        } else {
            const longlong2* sp = (const longlong2*)eidx;
            const longlong2* dp = (const longlong2*)((const long long*)eidx + E);
            longlong2 s01 = sp[2 * t], s23 = sp[2 * t + 1];
            longlong2 d01 = dp[2 * t], d23 = dp[2 * t + 1];
            s[0] = (int)s01.x; s[1] = (int)s01.y; s[2] = (int)s23.x; s[3] = (int)s23.y;
            d[0] = (int)d01.x; d[1] = (int)d01.y; d[2] = (int)d23.x; d[3] = (int)d23.y;
        }
        *(int4*)&g_sd[4 * t]     = make_int4(s[0], d[0], s[1], d[1]);
        *(int4*)&g_sd[4 * t + 2] = make_int4(s[2], d[2], s[3], d[3]);
        atomicAdd(&g_cnt[d[0]], 1);
        atomicAdd(&g_cnt[d[1]], 1);
        atomicAdd(&g_cnt[d[2]], 1);
        atomicAdd(&g_cnt[d[3]], 1);
    } else if (t < quarter + rem) {
        int e = E - rem + (t - quarter);
        int s, d;
        if (g_flag) {
            const int* q = (const int*)eidx;
            s = q[e]; d = q[E + e];
        } else {
            const long long* q = (const long long*)eidx;
            s = (int)q[e]; d = (int)q[E + e];
        }
        g_sd[e] = make_int2(s, d);
        atomicAdd(&g_cnt[d], 1);
    } else {
        int node = t - quarter - rem;
        if (node < n) {                // self loops
            g_sd[E + node] = make_int2(node, node);
            atomicAdd(&g_cnt[node], 1);
        }
    }
}

// 40-block scan: each block scans its 256 counts (block-local exclusive
// prefixes into g_rowptr/g_fill), last block (ticket) scans the 40 totals.
// Also RE-ZEROES g_cnt and g_ticket for the next call (invariant restore).
__global__ __launch_bounds__(256) void scan_kernel(int n) {
    __shared__ int wsum[8];
    __shared__ int lastflag;
    int b = blockIdx.x, t = threadIdx.x;
    int lane = t & 31, w = t >> 5;
    int idx = b * 256 + t;

    int v = g_cnt[idx];
    g_cnt[idx] = 0;                    // restore zero-invariant for next call
    // inclusive warp scan
    int incl = v;
#pragma unroll
    for (int o = 1; o < 32; o <<= 1) {
        int x = __shfl_up_sync(0xffffffffu, incl, o);
        if (lane >= o) incl += x;
    }
    if (lane == 31) wsum[w] = incl;
    __syncthreads();
    int woff = 0;
#pragma unroll
    for (int j = 0; j < 8; j++) woff += (j < w) ? wsum[j] : 0;
    int excl = woff + incl - v;        // block-local exclusive prefix

    if (idx <= n) g_rowptr[idx] = excl;
    if (idx < n)  g_fill[idx]   = excl;

    // block total -> last block computes block offsets
    if (t == 0) {
        int tot = 0;
#pragma unroll
        for (int j = 0; j < 8; j++) tot += wsum[j];
        g_blktot[b] = tot;
        __threadfence();
        unsigned tk = atomicAdd(&g_ticket, 1u);
        lastflag = (tk == NBLK - 1);
    }
    __syncthreads();
    if (lastflag && t == 0) {
        int run = 0;
#pragma unroll
        for (int j = 0; j < NBLK; j++) {
            g_blkoff[j] = run;
            run += g_blktot[j];
        }
        g_ticket = 0;                  // reset for next call
    }
}

// scatter srcs into CSR slots (2 edges per thread); global pos = local + blkoff
__global__ void scatter_kernel(int tot) {
    int t = blockIdx.x * blockDim.x + threadIdx.x;
    int half = tot >> 1;
    if (t < half) {
        int4 p = *(const int4*)&g_sd[2 * t];   // (s0,d0,s1,d1)
        int pos0 = atomicAdd(&g_fill[p.y], 1) + g_blkoff[p.y >> 8];
        g_csr[pos0] = p.x;
        int pos1 = atomicAdd(&g_fill[p.w], 1) + g_blkoff[p.w >> 8];
        g_csr[pos1] = p.z;
    } else if (2 * half + (t - half) < tot) {  // odd tail
        int2 p = g_sd[2 * half + (t - half)];
        int pos = atomicAdd(&g_fill[p.y], 1) + g_blkoff[p.y >> 8];
        g_csr[pos] = p.x;
    }
}

// h = seq @ W_comb^T.  BM=32 x 128 x BK=32, 128 threads, 4x8 microtile,
// cp.async double-buffered smem.  Epilogue: fp32 a_s/a_d + fp16 h store.
__global__ __launch_bounds__(128, 4) void gemm_h_kernel(
        const float* __restrict__ seq,
        const float* __restrict__ att_s,
        const float* __restrict__ att_d, int n) {
    __shared__ float As[2][BM][36];      // pitch 36 floats (16B-aligned rows)
    __shared__ float Bs[2][BK][OUT_FT];

    int bm  = blockIdx.x * BM;
    int tid = threadIdx.x;
    int tx  = tid & 15;          // col group
    int ty  = tid >> 4;          // 0..7 -> 4 rows each
    int r0  = ty * 4;

    auto issue = [&](int kt, int buf) {
        int k0 = kt * BK;
#pragma unroll
        for (int i = 0; i < 2; i++) {                 // A: 32x32 = 256 x 16B
            int idx = tid + i * 128;
            int r = idx >> 3, c4 = (idx & 7) << 2;
            int row = bm + r; if (row >= n) row = n - 1;
            cp16(&As[buf][r][c4], &seq[row * IN_FT + k0 + c4]);
        }
#pragma unroll
        for (int i = 0; i < 8; i++) {                 // B: 32x128 = 1024 x 16B
            int idx = tid + i * 128;
            int kk = idx >> 5, o4 = (idx & 31) << 2;
            cp16(&Bs[buf][kk][o4], &g_wcT[(k0 + kk) * OUT_FT + o4]);
        }
        cp_commit();
    };

    float acc[4][8];
#pragma unroll
    for (int i = 0; i < 4; i++)
#pragma unroll
        for (int j = 0; j < 8; j++) acc[i][j] = 0.f;

    issue(0, 0);
    issue(1, 1);

    for (int kt = 0; kt < NKT; kt++) {
        if (kt < NKT - 1) cp_wait<1>(); else cp_wait<0>();
        __syncthreads();
        int buf = kt & 1;
#pragma unroll
        for (int kk = 0; kk < BK; kk++) {
            float a[4];
#pragma unroll
            for (int i = 0; i < 4; i++) a[i] = As[buf][r0 + i][kk];
            // thread's 8 cols: {tx*4..+3} and {64+tx*4..+3} (conflict-free LDS.128)
            float4 b0 = *(const float4*)&Bs[buf][kk][tx * 4];
            float4 b1 = *(const float4*)&Bs[buf][kk][64 + tx * 4];
            float b[8] = {b0.x, b0.y, b0.z, b0.w, b1.x, b1.y, b1.z, b1.w};
#pragma unroll
            for (int i = 0; i < 4; i++)
#pragma unroll
                for (int j = 0; j < 8; j++)
                    acc[i][j] += a[i] * b[j];
        }
        __syncthreads();
        if (kt + 2 < NKT) issue(kt + 2, buf);
    }

    // epilogue: fp16 h store + fused fp32 attention logits
    float as8[8], ad8[8];
#pragma unroll
    for (int j = 0; j < 4; j++) {
        as8[j]     = att_s[tx * 4 + j];
        as8[4 + j] = att_s[64 + tx * 4 + j];
        ad8[j]     = att_d[tx * 4 + j];
        ad8[4 + j] = att_d[64 + tx * 4 + j];
    }
#pragma unroll
    for (int i = 0; i < 4; i++) {
        int row = bm + r0 + i;
        bool valid = (row < n);
        float vs = 0.f, vd = 0.f;
#pragma unroll
        for (int j = 0; j < 8; j++) { vs += acc[i][j] * as8[j]; vd += acc[i][j] * ad8[j]; }
        if (valid) {
            __half2 p0 = __floats2half2_rn(acc[i][0], acc[i][1]);
            __half2 p1 = __floats2half2_rn(acc[i][2], acc[i][3]);
            __half2 p2 = __floats2half2_rn(acc[i][4], acc[i][5]);
            __half2 p3 = __floats2half2_rn(acc[i][6], acc[i][7]);
            *(uint2*)&g_hh[row * OUT_FT + tx * 4]      = make_uint2(h2_bits(p0), h2_bits(p1));
            *(uint2*)&g_hh[row * OUT_FT + 64 + tx * 4] = make_uint2(h2_bits(p2), h2_bits(p3));
        }
#pragma unroll
        for (int o = 1; o < 16; o <<= 1) {
            vs += __shfl_xor_sync(0xffffffffu, vs, o);
            vd += __shfl_xor_sync(0xffffffffu, vd, o);
        }
        if (valid && tx == 0) { g_as[row] = vs; g_ad[row] = vd; }
    }
}

// One block (128 threads) per destination node: segment softmax + weighted sum.
// Gathers fp16 h rows (8B per lane per edge), accumulates in fp32.
__global__ __launch_bounds__(128) void aggregate_kernel(
        const float* __restrict__ gat_bias,
        const float* __restrict__ bias,
        const float* __restrict__ prelu_a,
        float* __restrict__ out, int n) {
    int d = blockIdx.x;
    if (d >= n) return;
    int tid   = threadIdx.x;
    int w     = tid >> 5, lane = tid & 31;
    int start = g_rowptr[d]     + g_blkoff[d >> 8];
    int end   = g_rowptr[d + 1] + g_blkoff[(d + 1) >> 8];
    int deg   = end - start;
    float ad  = g_ad[d];

    __shared__ float e_sh[MAXD];
    __shared__ int   s_sh[MAXD];
    __shared__ float red[4];
    __shared__ float accsh[4][OUT_FT];

    if (deg <= MAXD) {
        // load + leaky-relu + max
        float lm = -1e30f;
        for (int i = tid; i < deg; i += 128) {
            int s = g_csr[start + i];
            float e = g_as[s] + ad;
            e = (e >= 0.f) ? e : 0.2f * e;
            s_sh[i] = s; e_sh[i] = e;
            lm = fmaxf(lm, e);
        }
#pragma unroll
        for (int o = 16; o > 0; o >>= 1)
            lm = fmaxf(lm, __shfl_xor_sync(0xffffffffu, lm, o));
        if (lane == 0) red[w] = lm;
        __syncthreads();
        float m = fmaxf(fmaxf(red[0], red[1]), fmaxf(red[2], red[3]));
        __syncthreads();

        // exp + denom
        float ls = 0.f;
        for (int i = tid; i < deg; i += 128) {
            float p = __expf(e_sh[i] - m);
            e_sh[i] = p;
            ls += p;
        }
#pragma unroll
        for (int o = 16; o > 0; o >>= 1)
            ls += __shfl_xor_sync(0xffffffffu, ls, o);
        if (lane == 0) red[w] = ls;
        __syncthreads();
        float denom = red[0] + red[1] + red[2] + red[3];

        // warp-parallel accumulation: warp w takes edges w, w+4, ...; lane = 4 features
        float4 a4 = make_float4(0.f, 0.f, 0.f, 0.f);
        for (int j = w; j < deg; j += 4) {
            float p = e_sh[j];
            uint2 hv = *(const uint2*)&g_hh[s_sh[j] * OUT_FT + lane * 4];
            float2 f0 = __half22float2(*(const __half2*)&hv.x);
            float2 f1 = __half22float2(*(const __half2*)&hv.y);
            a4.x += p * f0.x; a4.y += p * f0.y; a4.z += p * f1.x; a4.w += p * f1.y;
        }
        *(float4*)&accsh[w][lane * 4] = a4;
        __syncthreads();
        float sum = accsh[0][tid] + accsh[1][tid] + accsh[2][tid] + accsh[3][tid];

        float o_ = sum / (denom + 1e-16f) + gat_bias[tid] + bias[tid];
        float a  = prelu_a[0];
        out[d * OUT_FT + tid] = (o_ >= 0.f) ? o_ : a * o_;
    } else {
        // generic fallback: feature-per-thread, chunked path
        float lm = -1e30f;
        for (int i = start + tid; i < end; i += 128) {
            float e = g_as[g_csr[i]] + ad;
            e = (e >= 0.f) ? e : 0.2f * e;
            lm = fmaxf(lm, e);
        }
#pragma unroll
        for (int o = 16; o > 0; o >>= 1)
            lm = fmaxf(lm, __shfl_xor_sync(0xffffffffu, lm, o));
        if (lane == 0) red[w] = lm;
        __syncthreads();
        float m = fmaxf(fmaxf(red[0], red[1]), fmaxf(red[2], red[3]));
        __syncthreads();

        float ls = 0.f;
        for (int i = start + tid; i < end; i += 128) {
            float e = g_as[g_csr[i]] + ad;
            e = (e >= 0.f) ? e : 0.2f * e;
            ls += __expf(e - m);
        }
#pragma unroll
        for (int o = 16; o > 0; o >>= 1)
            ls += __shfl_xor_sync(0xffffffffu, ls, o);
        if (lane == 0) red[w] = ls;
        __syncthreads();
        float denom = red[0] + red[1] + red[2] + red[3];
        __syncthreads();

        float acc = 0.f;
        for (int c = start; c < end; c += 128) {
            int i = c + tid;
            if (i < end) {
                int s = g_csr[i];
                float e = g_as[s] + ad;
                e = (e >= 0.f) ? e : 0.2f * e;
                e_sh[tid] = __expf(e - m);
                s_sh[tid] = s;
            }
            __syncthreads();
            int len = min(128, end - c);
            for (int j = 0; j < len; j++)
                acc += e_sh[j] * __half2float(g_hh[s_sh[j] * OUT_FT + tid]);
            __syncthreads();
        }
        float o_ = acc / (denom + 1e-16f) + gat_bias[tid] + bias[tid];
        float a  = prelu_a[0];
        out[d * OUT_FT + tid] = (o_ >= 0.f) ? o_ : a * o_;
    }
}

// ---------------- launch ----------------
extern "C" void kernel_launch(void* const* d_in, const int* in_sizes, int n_in,
                              void* d_out, int out_size) {
    const float* seq      = (const float*)d_in[0];
    const void*  eidx     = d_in[1];
    const float* Wfc      = (const float*)d_in[2];
    const float* Wgat     = (const float*)d_in[3];
    const float* att_src  = (const float*)d_in[4];
    const float* att_dst  = (const float*)d_in[5];
    const float* gat_bias = (const float*)d_in[6];
    const float* bias     = (const float*)d_in[7];
    const float* prelu_a  = (const float*)d_in[8];
    float* out = (float*)d_out;

    int n = in_sizes[0] / IN_FT;     // 10000
    int E = in_sizes[1] / 2;         // 640000
    int tot = E + n;

    setup_kernel<<<129, 128>>>(Wgat, Wfc, (const int*)eidx, E);
    int cnt_threads = E / 4 + (E & 3) + n;
    count_kernel<<<(cnt_threads + 255) / 256, 256>>>(eidx, E, n);
    gemm_h_kernel<<<(n + BM - 1) / BM, 128>>>(seq, att_src, att_dst, n);
    scan_kernel<<<NBLK, 256>>>(n);
    int sc_threads = tot / 2 + 1;
    scatter_kernel<<<(sc_threads + 255) / 256, 256>>>(tot);
    aggregate_kernel<<<n, 128>>>(gat_bias, bias, prelu_a, out, n);
}

// round 14
// speedup vs baseline: 1.1949x; 1.0792x over previous
#include <cuda_runtime.h>
#include <cuda_bf16.h>
#include <cuda_fp16.h>
#include <mma.h>
#include <cstdint>

using namespace nvcuda;

// Problem constants (shapes are fixed by the reference)
#define NN      10000
#define EE      640000
#define TOT_E   (EE + NN)      // edges + self loops
#define IN_FT   512
#define OUT_FT  128

#define MAXD 512
#define SCAN_TOT 10240         // padded count array (40 * 256 >= NN)
#define NBLK 40                // scan blocks
#define KCH 32                 // K per GEMM chunk
#define NCHUNK (IN_FT / KCH)   // 16
#define BMG 64                 // GEMM rows per CTA

// smem layout inside the union buffer (bytes)
#define SA_PITCH 40            // halfs per A row (32 + 8 pad)
#define SB_PITCH 136           // halfs per B row (128 + 8 pad)
#define OFF_AHI 0
#define OFF_ALO 5120           // 64*40*2
#define OFF_BHI 10240
#define OFF_BLO 18944          // 10240 + 32*136*2
#define UBUF_SZ 32768          // >= max(27648 compute, 64*128*4 epilogue)

// ---------------- device scratch (no allocation allowed) ----------------
__device__ __half g_hh[NN * OUT_FT];       // h in fp16 (aggregate gathers)
__device__ __half g_wbhi[IN_FT * OUT_FT];  // W_comb^T hi halves, [k][n]
__device__ __half g_wblo[IN_FT * OUT_FT];  // W_comb^T lo halves, [k][n]
__device__ float g_as[NN];                 // h @ att_src (fp32)
__device__ float g_ad[NN];                 // h @ att_dst (fp32)
__device__ int   g_cnt[SCAN_TOT];          // per-dst counts; zero at call entry
__device__ int   g_rowptr[NN + 1];         // block-LOCAL exclusive prefixes
__device__ int   g_fill[NN];               // scatter cursors (block-local)
__device__ int   g_blktot[NBLK];
__device__ int   g_blkoff[NBLK];
__device__ unsigned g_ticket;              // reset by scan each call
__device__ int   g_csr[TOT_E];
__device__ int2  g_sd[TOT_E];
__device__ int   g_flag = 0;               // 1 = edge_index is int32 (OR-only)

// ---------------- helpers ----------------
__device__ __forceinline__ void cp16(void* dst, const void* src) {
    uint32_t d = (uint32_t)__cvta_generic_to_shared(dst);
    asm volatile("cp.async.cg.shared.global [%0], [%1], 16;\n" :: "r"(d), "l"(src));
}
__device__ __forceinline__ void cp_commit() {
    asm volatile("cp.async.commit_group;\n");
}
template<int N> __device__ __forceinline__ void cp_wait() {
    asm volatile("cp.async.wait_group %0;\n" :: "n"(N));
}

// ---------------- setup: wcomb -> fp16 hi/lo split + dtype detect ----------
// Blocks 0..127: 32 o-tiles (4 outputs) x 4 k-tiles (128 k's). Block 128: detect.
__global__ __launch_bounds__(128) void setup_kernel(
        const float* __restrict__ Wgat,
        const float* __restrict__ Wfc,
        const int* __restrict__ ep, int E) {
    int b = blockIdx.x;
    if (b < 128) {
        int ot = b >> 2;               // o-tile: 4 outputs
        int kt = b & 3;                // k-tile: 128 k's
        int k  = kt * 128 + threadIdx.x;
        __shared__ float ws[4][128];
        for (int i = threadIdx.x; i < 4 * 128; i += 128)
            ws[i >> 7][i & 127] = Wgat[(ot * 4 + (i >> 7)) * OUT_FT + (i & 127)];
        __syncthreads();
        float acc[4] = {0.f, 0.f, 0.f, 0.f};
#pragma unroll 8
        for (int m = 0; m < OUT_FT; m++) {
            float wf = Wfc[m * IN_FT + k];
#pragma unroll
            for (int o = 0; o < 4; o++) acc[o] += ws[o][m] * wf;
        }
#pragma unroll
        for (int o = 0; o < 4; o++) {
            int nidx = ot * 4 + o;
            float w  = acc[o];
            __half hi = __float2half_rn(w);
            __half lo = __float2half_rn(w - __half2float(hi));
            g_wbhi[k * OUT_FT + nidx] = hi;
            g_wblo[k * OUT_FT + nidx] = lo;
        }
    } else {
        // detect: int64 node ids < 2^31 have zero high words
#pragma unroll
        for (int i = 0; i < 8; i++) {
            int j = threadIdx.x * 8 + i;
            if (j < 1024 && j < E && ep[2 * j + 1] != 0) {
                atomicOr(&g_flag, 1);
                break;
            }
        }
    }
}

// decode edges (4 per thread, vectorized), count degrees, stage (src,dst)
__global__ void count_kernel(const void* eidx, int E, int n) {
    int t = blockIdx.x * blockDim.x + threadIdx.x;
    int quarter = E >> 2;
    int rem = E & 3;
    if (t < quarter) {
        int s[4], d[4];
        if (g_flag) {
            int4 ss = ((const int4*)eidx)[t];
            int4 dd = ((const int4*)((const int*)eidx + E))[t];
            s[0] = ss.x; s[1] = ss.y; s[2] = ss.z; s[3] = ss.w;
            d[0] = dd.x; d[1] = dd.y; d[2] = dd.z; d[3] = dd.w;
        } else {
            const longlong2* sp = (const longlong2*)eidx;
            const longlong2* dp = (const longlong2*)((const long long*)eidx + E);
            longlong2 s01 = sp[2 * t], s23 = sp[2 * t + 1];
            longlong2 d01 = dp[2 * t], d23 = dp[2 * t + 1];
            s[0] = (int)s01.x; s[1] = (int)s01.y; s[2] = (int)s23.x; s[3] = (int)s23.y;
            d[0] = (int)d01.x; d[1] = (int)d01.y; d[2] = (int)d23.x; d[3] = (int)d23.y;
        }
        *(int4*)&g_sd[4 * t]     = make_int4(s[0], d[0], s[1], d[1]);
        *(int4*)&g_sd[4 * t + 2] = make_int4(s[2], d[2], s[3], d[3]);
        atomicAdd(&g_cnt[d[0]], 1);
        atomicAdd(&g_cnt[d[1]], 1);
        atomicAdd(&g_cnt[d[2]], 1);
        atomicAdd(&g_cnt[d[3]], 1);
    } else if (t < quarter + rem) {
        int e = E - rem + (t - quarter);
        int s, d;
        if (g_flag) {
            const int* q = (const int*)eidx;
            s = q[e]; d = q[E + e];
        } else {
            const long long* q = (const long long*)eidx;
            s = (int)q[e]; d = (int)q[E + e];
        }
        g_sd[e] = make_int2(s, d);
        atomicAdd(&g_cnt[d], 1);
    } else {
        int node = t - quarter - rem;
        if (node < n) {                // self loops
            g_sd[E + node] = make_int2(node, node);
            atomicAdd(&g_cnt[node], 1);
        }
    }
}

// 40-block scan; last block (ticket) scans the 40 totals via smem staging.
// Re-zeroes g_cnt and g_ticket for the next call.
__global__ __launch_bounds__(256) void scan_kernel(int n) {
    __shared__ int wsum[8];
    __shared__ int lastflag;
    __shared__ int sh_bt[NBLK];
    int b = blockIdx.x, t = threadIdx.x;
    int lane = t & 31, w = t >> 5;
    int idx = b * 256 + t;

    int v = g_cnt[idx];
    g_cnt[idx] = 0;                    // restore zero-invariant for next call
    int incl = v;
#pragma unroll
    for (int o = 1; o < 32; o <<= 1) {
        int x = __shfl_up_sync(0xffffffffu, incl, o);
        if (lane >= o) incl += x;
    }
    if (lane == 31) wsum[w] = incl;
    __syncthreads();
    int woff = 0;
#pragma unroll
    for (int j = 0; j < 8; j++) woff += (j < w) ? wsum[j] : 0;
    int excl = woff + incl - v;

    if (idx <= n) g_rowptr[idx] = excl;
    if (idx < n)  g_fill[idx]   = excl;

    if (t == 0) {
        int tot = 0;
#pragma unroll
        for (int j = 0; j < 8; j++) tot += wsum[j];
        g_blktot[b] = tot;
        __threadfence();
        unsigned tk = atomicAdd(&g_ticket, 1u);
        lastflag = (tk == NBLK - 1);
    }
    __syncthreads();
    if (lastflag) {
        if (t < NBLK) sh_bt[t] = g_blktot[t];   // parallel loads
    }
    __syncthreads();
    if (lastflag && t == 0) {
        int run = 0;
#pragma unroll
        for (int j = 0; j < NBLK; j++) {
            g_blkoff[j] = run;
            run += sh_bt[j];
        }
        g_ticket = 0;
    }
}

// scatter srcs into CSR slots (2 edges per thread); global pos = local + blkoff
__global__ void scatter_kernel(int tot) {
    int t = blockIdx.x * blockDim.x + threadIdx.x;
    int half = tot >> 1;
    if (t < half) {
        int4 p = *(const int4*)&g_sd[2 * t];
        int pos0 = atomicAdd(&g_fill[p.y], 1) + g_blkoff[p.y >> 8];
        g_csr[pos0] = p.x;
        int pos1 = atomicAdd(&g_fill[p.w], 1) + g_blkoff[p.w >> 8];
        g_csr[pos1] = p.z;
    } else if (2 * half + (t - half) < tot) {
        int2 p = g_sd[2 * half + (t - half)];
        int pos = atomicAdd(&g_fill[p.y], 1) + g_blkoff[p.y >> 8];
        g_csr[pos] = p.x;
    }
}

// ---------------- wmma GEMM: h = seq @ W_comb^T (split-fp16 x3) --------------
// CTA: 64 rows x 128 cols, 4 warps (16 rows each, 8 wmma n-tiles).
// K = 512 in 16 chunks of 32 (2 wmma k-steps each).
// acc fp32 in fragments; epilogue via smem: fp16 h + fp32 a_s/a_d.
__global__ __launch_bounds__(128) void gemm_wmma_kernel(
        const float* __restrict__ seq,
        const float* __restrict__ att_s,
        const float* __restrict__ att_d, int n) {
    __shared__ __align__(16) unsigned char ubuf[UBUF_SZ];
    __shared__ float s_att[2][OUT_FT];

    __half* sAhi = (__half*)(ubuf + OFF_AHI);
    __half* sAlo = (__half*)(ubuf + OFF_ALO);
    __half* sBhi = (__half*)(ubuf + OFF_BHI);
    __half* sBlo = (__half*)(ubuf + OFF_BLO);
    float*  sC   = (float*)ubuf;

    int tid = threadIdx.x;
    int w   = tid >> 5;
    int bm  = blockIdx.x * BMG;

    if (tid < OUT_FT) {
        s_att[0][tid] = att_s[tid];
        s_att[1][tid] = att_d[tid];
    }

    wmma::fragment<wmma::accumulator, 16, 16, 16, float> acc[8];
#pragma unroll
    for (int nt = 0; nt < 8; nt++) wmma::fill_fragment(acc[nt], 0.f);

    for (int c = 0; c < NCHUNK; c++) {
        int k0 = c * KCH;
        __syncthreads();               // protect smem from previous iteration
        // B chunk: cp.async of pre-split halves (32 rows x 256B each)
#pragma unroll
        for (int i = 0; i < 4; i++) {
            int idx = tid + i * 128;   // 0..511
            int r = idx >> 4, c16 = idx & 15;
            cp16((unsigned char*)sBhi + r * (SB_PITCH * 2) + c16 * 16,
                 (const unsigned char*)&g_wbhi[(k0 + r) * OUT_FT] + c16 * 16);
            cp16((unsigned char*)sBlo + r * (SB_PITCH * 2) + c16 * 16,
                 (const unsigned char*)&g_wblo[(k0 + r) * OUT_FT] + c16 * 16);
        }
        cp_commit();
        // A chunk: load fp32, split hi/lo to smem
#pragma unroll
        for (int i = 0; i < 4; i++) {
            int idx = tid + i * 128;   // 0..511 float4s = 64 rows x 8
            int m = idx >> 3, kk4 = (idx & 7) << 2;
            int row = bm + m; if (row >= n) row = n - 1;
            float4 v = *(const float4*)&seq[row * IN_FT + k0 + kk4];
            __half h0 = __float2half_rn(v.x), h1 = __float2half_rn(v.y);
            __half h2 = __float2half_rn(v.z), h3 = __float2half_rn(v.w);
            __half l0 = __float2half_rn(v.x - __half2float(h0));
            __half l1 = __float2half_rn(v.y - __half2float(h1));
            __half l2 = __float2half_rn(v.z - __half2float(h2));
            __half l3 = __float2half_rn(v.w - __half2float(h3));
            __half2 hA = __halves2half2(h0, h1), hB = __halves2half2(h2, h3);
            __half2 lA = __halves2half2(l0, l1), lB = __halves2half2(l2, l3);
            *(uint2*)&sAhi[m * SA_PITCH + kk4] =
                make_uint2(*(uint32_t*)&hA, *(uint32_t*)&hB);
            *(uint2*)&sAlo[m * SA_PITCH + kk4] =
                make_uint2(*(uint32_t*)&lA, *(uint32_t*)&lB);
        }
        cp_wait<0>();
        __syncthreads();

#pragma unroll
        for (int kk = 0; kk < 2; kk++) {
            wmma::fragment<wmma::matrix_a, 16, 16, 16, __half, wmma::row_major> fa_hi, fa_lo;
            wmma::load_matrix_sync(fa_hi, &sAhi[(w * 16) * SA_PITCH + kk * 16], SA_PITCH);
            wmma::load_matrix_sync(fa_lo, &sAlo[(w * 16) * SA_PITCH + kk * 16], SA_PITCH);
#pragma unroll
            for (int nt = 0; nt < 8; nt++) {
                wmma::fragment<wmma::matrix_b, 16, 16, 16, __half, wmma::row_major> fb_hi, fb_lo;
                wmma::load_matrix_sync(fb_hi, &sBhi[(kk * 16) * SB_PITCH + nt * 16], SB_PITCH);
                wmma::load_matrix_sync(fb_lo, &sBlo[(kk * 16) * SB_PITCH + nt * 16], SB_PITCH);
                wmma::mma_sync(acc[nt], fa_hi, fb_hi, acc[nt]);
                wmma::mma_sync(acc[nt], fa_hi, fb_lo, acc[nt]);
                wmma::mma_sync(acc[nt], fa_lo, fb_hi, acc[nt]);
            }
        }
    }
    __syncthreads();

    // epilogue: dump acc to smem float [64][128], then per-row output
#pragma unroll
    for (int nt = 0; nt < 8; nt++)
        wmma::store_matrix_sync(&sC[(w * 16) * OUT_FT + nt * 16], acc[nt],
                                OUT_FT, wmma::mem_row_major);
    __syncthreads();

    if (tid < BMG) {
        int g = bm + tid;
        if (g < n) {
            const float* row = &sC[tid * OUT_FT];
            float vs = 0.f, vd = 0.f;
            __half* dst = &g_hh[g * OUT_FT];
#pragma unroll 16
            for (int j = 0; j < OUT_FT; j += 2) {
                float f0 = row[j], f1 = row[j + 1];
                vs += f0 * s_att[0][j] + f1 * s_att[0][j + 1];
                vd += f0 * s_att[1][j] + f1 * s_att[1][j + 1];
                __half2 hp = __floats2half2_rn(f0, f1);
                *(__half2*)&dst[j] = hp;
            }
            g_as[g] = vs;
            g_ad[g] = vd;
        }
    }
}

// One block (128 threads) per destination node: segment softmax + weighted sum.
__global__ __launch_bounds__(128) void aggregate_kernel(
        const float* __restrict__ gat_bias,
        const float* __restrict__ bias,
        const float* __restrict__ prelu_a,
        float* __restrict__ out, int n) {
    int d = blockIdx.x;
    if (d >= n) return;
    int tid   = threadIdx.x;
    int w     = tid >> 5, lane = tid & 31;
    int start = g_rowptr[d]     + g_blkoff[d >> 8];
    int end   = g_rowptr[d + 1] + g_blkoff[(d + 1) >> 8];
    int deg   = end - start;
    float ad  = g_ad[d];

    __shared__ float e_sh[MAXD];
    __shared__ int   s_sh[MAXD];
    __shared__ float red[4];
    __shared__ float accsh[4][OUT_FT];

    if (deg <= MAXD) {
        float lm = -1e30f;
        for (int i = tid; i < deg; i += 128) {
            int s = g_csr[start + i];
            float e = g_as[s] + ad;
            e = (e >= 0.f) ? e : 0.2f * e;
            s_sh[i] = s; e_sh[i] = e;
            lm = fmaxf(lm, e);
        }
#pragma unroll
        for (int o = 16; o > 0; o >>= 1)
            lm = fmaxf(lm, __shfl_xor_sync(0xffffffffu, lm, o));
        if (lane == 0) red[w] = lm;
        __syncthreads();
        float m = fmaxf(fmaxf(red[0], red[1]), fmaxf(red[2], red[3]));
        __syncthreads();

        float ls = 0.f;
        for (int i = tid; i < deg; i += 128) {
            float p = __expf(e_sh[i] - m);
            e_sh[i] = p;
            ls += p;
        }
#pragma unroll
        for (int o = 16; o > 0; o >>= 1)
            ls += __shfl_xor_sync(0xffffffffu, ls, o);
        if (lane == 0) red[w] = ls;
        __syncthreads();
        float denom = red[0] + red[1] + red[2] + red[3];

        float4 a4 = make_float4(0.f, 0.f, 0.f, 0.f);
        for (int j = w; j < deg; j += 4) {
            float p = e_sh[j];
            uint2 hv = *(const uint2*)&g_hh[s_sh[j] * OUT_FT + lane * 4];
            float2 f0 = __half22float2(*(const __half2*)&hv.x);
            float2 f1 = __half22float2(*(const __half2*)&hv.y);
            a4.x += p * f0.x; a4.y += p * f0.y; a4.z += p * f1.x; a4.w += p * f1.y;
        }
        *(float4*)&accsh[w][lane * 4] = a4;
        __syncthreads();
        float sum = accsh[0][tid] + accsh[1][tid] + accsh[2][tid] + accsh[3][tid];

        float o_ = sum / (denom + 1e-16f) + gat_bias[tid] + bias[tid];
        float a  = prelu_a[0];
        out[d * OUT_FT + tid] = (o_ >= 0.f) ? o_ : a * o_;
    } else {
        float lm = -1e30f;
        for (int i = start + tid; i < end; i += 128) {
            float e = g_as[g_csr[i]] + ad;
            e = (e >= 0.f) ? e : 0.2f * e;
            lm = fmaxf(lm, e);
        }
#pragma unroll
        for (int o = 16; o > 0; o >>= 1)
            lm = fmaxf(lm, __shfl_xor_sync(0xffffffffu, lm, o));
        if (lane == 0) red[w] = lm;
        __syncthreads();
        float m = fmaxf(fmaxf(red[0], red[1]), fmaxf(red[2], red[3]));
        __syncthreads();

        float ls = 0.f;
        for (int i = start + tid; i < end; i += 128) {
            float e = g_as[g_csr[i]] + ad;
            e = (e >= 0.f) ? e : 0.2f * e;
            ls += __expf(e - m);
        }
#pragma unroll
        for (int o = 16; o > 0; o >>= 1)
            ls += __shfl_xor_sync(0xffffffffu, ls, o);
        if (lane == 0) red[w] = ls;
        __syncthreads();
        float denom = red[0] + red[1] + red[2] + red[3];
        __syncthreads();

        float acc = 0.f;
        for (int c = start; c < end; c += 128) {
            int i = c + tid;
            if (i < end) {
                int s = g_csr[i];
                float e = g_as[s] + ad;
                e = (e >= 0.f) ? e : 0.2f * e;
                e_sh[tid] = __expf(e - m);
                s_sh[tid] = s;
            }
            __syncthreads();
            int len = min(128, end - c);
            for (int j = 0; j < len; j++)
                acc += e_sh[j] * __half2float(g_hh[s_sh[j] * OUT_FT + tid]);
            __syncthreads();
        }
        float o_ = acc / (denom + 1e-16f) + gat_bias[tid] + bias[tid];
        float a  = prelu_a[0];
        out[d * OUT_FT + tid] = (o_ >= 0.f) ? o_ : a * o_;
    }
}

// ---------------- launch ----------------
extern "C" void kernel_launch(void* const* d_in, const int* in_sizes, int n_in,
                              void* d_out, int out_size) {
    const float* seq      = (const float*)d_in[0];
    const void*  eidx     = d_in[1];
    const float* Wfc      = (const float*)d_in[2];
    const float* Wgat     = (const float*)d_in[3];
    const float* att_src  = (const float*)d_in[4];
    const float* att_dst  = (const float*)d_in[5];
    const float* gat_bias = (const float*)d_in[6];
    const float* bias     = (const float*)d_in[7];
    const float* prelu_a  = (const float*)d_in[8];
    float* out = (float*)d_out;

    int n = in_sizes[0] / IN_FT;     // 10000
    int E = in_sizes[1] / 2;         // 640000
    int tot = E + n;

    setup_kernel<<<129, 128>>>(Wgat, Wfc, (const int*)eidx, E);
    int cnt_threads = E / 4 + (E & 3) + n;
    count_kernel<<<(cnt_threads + 255) / 256, 256>>>(eidx, E, n);
    gemm_wmma_kernel<<<(n + BMG - 1) / BMG, 128>>>(seq, att_src, att_dst, n);
    scan_kernel<<<NBLK, 256>>>(n);
    int sc_threads = tot / 2 + 1;
    scatter_kernel<<<(sc_threads + 255) / 256, 256>>>(tot);
    aggregate_kernel<<<n, 128>>>(gat_bias, bias, prelu_a, out, n);
}